// round 2
// baseline (speedup 1.0000x reference)
#include <cuda_runtime.h>

typedef unsigned long long ull;
#define BSZ 2
#define NN 50000
#define NEg 400000
#define TPB 256
#define TILE 16

__device__ float g_Pmsg[BSZ * NN * 128];
__device__ float g_Pupd[BSZ * NN * 128];
__device__ float g_agg[BSZ * NN * 128];
__device__ float g_den[BSZ * NN];

__device__ __forceinline__ ull fma2(ull a, ull b, ull c) {
    ull d; asm("fma.rn.f32x2 %0, %1, %2, %3;" : "=l"(d) : "l"(a), "l"(b), "l"(c)); return d;
}
__device__ __forceinline__ ull pk2(float x, float y) {
    ull r; asm("mov.b64 %0, {%1, %2};" : "=l"(r) : "f"(x), "f"(y)); return r;
}
__device__ __forceinline__ ull dup2(float x) {
    ull r; asm("mov.b64 %0, {%1, %1};" : "=l"(r) : "f"(x)); return r;
}
__device__ __forceinline__ float2 up2(ull v) {
    float2 r; asm("mov.b64 {%0, %1}, %2;" : "=f"(r.x), "=f"(r.y) : "l"(v)); return r;
}
__device__ __forceinline__ float silu_f(float x) { return x / (1.f + __expf(-x)); }
__device__ __forceinline__ void red4(float* p, float a, float b, float c, float d) {
    asm volatile("red.global.add.v4.f32 [%0], {%1,%2,%3,%4};"
                 :: "l"(p), "f"(a), "f"(b), "f"(c), "f"(d) : "memory");
}

// 64->128 GEMM stage: hidden in (H0,H1) across lanes, W2 in smem as ull pairs.
__device__ __forceinline__ void gemm2(const ull* w2u, int l, float2 H0, float2 H1,
                                      ull& m0a, ull& m0b, ull& m1a, ull& m1b) {
#pragma unroll 4
    for (int j = 0; j < 32; j++) {
        ull wlo = w2u[(j * 32 + l) * 2], whi = w2u[(j * 32 + l) * 2 + 1];
        ull d0 = dup2(__shfl_sync(0xffffffffu, H0.x, j));
        ull d1 = dup2(__shfl_sync(0xffffffffu, H1.x, j));
        m0a = fma2(d0, wlo, m0a); m0b = fma2(d0, whi, m0b);
        m1a = fma2(d1, wlo, m1a); m1b = fma2(d1, whi, m1b);
    }
#pragma unroll 4
    for (int j = 0; j < 32; j++) {
        ull wlo = w2u[((j + 32) * 32 + l) * 2], whi = w2u[((j + 32) * 32 + l) * 2 + 1];
        ull d0 = dup2(__shfl_sync(0xffffffffu, H0.y, j));
        ull d1 = dup2(__shfl_sync(0xffffffffu, H1.y, j));
        m0a = fma2(d0, wlo, m0a); m0b = fma2(d0, whi, m0b);
        m1a = fma2(d1, wlo, m1a); m1b = fma2(d1, whi, m1b);
    }
}

__global__ void k_init() {
    float4 z = make_float4(0.f, 0.f, 0.f, 0.f);
    for (int i = blockIdx.x * blockDim.x + threadIdx.x; i < BSZ * NN * 32; i += gridDim.x * blockDim.x)
        ((float4*)g_agg)[i] = z;
    for (int i = blockIdx.x * blockDim.x + threadIdx.x; i < BSZ * NN; i += gridDim.x * blockDim.x)
        g_den[i] = 0.f;
}

// per-node precompute of sender/receiver partial GEMMs (rows 0:256 of W1)
__global__ void k_node_pre(const float* __restrict__ V, const float* __restrict__ Wg, float* __restrict__ P) {
    extern __shared__ float sm[];
    float4* sW = (float4*)sm;           // 128*32 float4 = 64KB
    float* sV = sm + 128 * 32 * 4;      // 16*128
    for (int i = threadIdx.x; i < 128 * 32; i += TPB) {
        int k = i >> 5, l = i & 31;
        sW[i] = make_float4(Wg[k * 64 + l], Wg[k * 64 + l + 32],
                            Wg[(128 + k) * 64 + l], Wg[(128 + k) * 64 + l + 32]);
    }
    __syncthreads();
    const ull* sWu = (const ull*)sW;
    const int warp = threadIdx.x >> 5, l = threadIdx.x & 31;
    const int ntiles = (BSZ * NN) / TILE;
    for (int t = blockIdx.x; t < ntiles; t += gridDim.x) {
        __syncthreads();
        const float4* Vg = (const float4*)V + (size_t)t * TILE * 32;
        for (int i = threadIdx.x; i < TILE * 32; i += TPB) ((float4*)sV)[i] = __ldcs(Vg + i);
        __syncthreads();
        const int r0 = 2 * warp;
        ull a0 = 0ULL, b0 = 0ULL, a1 = 0ULL, b1 = 0ULL;
        const float4* v0p = (const float4*)(sV + r0 * 128);
        const float4* v1p = v0p + 32;
#pragma unroll 4
        for (int k4 = 0; k4 < 32; k4++) {
            float ea[4], eb[4];
            *(float4*)ea = v0p[k4]; *(float4*)eb = v1p[k4];
#pragma unroll
            for (int i = 0; i < 4; i++) {
                int k = k4 * 4 + i;
                ull wa = sWu[(k * 32 + l) * 2], wb = sWu[(k * 32 + l) * 2 + 1];
                a0 = fma2(dup2(ea[i]), wa, a0); b0 = fma2(dup2(ea[i]), wb, b0);
                a1 = fma2(dup2(eb[i]), wa, a1); b1 = fma2(dup2(eb[i]), wb, b1);
            }
        }
        float2 A0 = up2(a0), B0 = up2(b0), A1 = up2(a1), B1 = up2(b1);
        float* p0 = P + ((size_t)t * TILE + r0) * 128;
        p0[l] = A0.x; p0[l + 32] = A0.y; p0[64 + l] = B0.x; p0[96 + l] = B0.y;
        float* p1 = p0 + 128;
        p1[l] = A1.x; p1[l + 32] = A1.y; p1[64 + l] = B1.x; p1[96 + l] = B1.y;
    }
}

// fused edge MLP (+ attention & scatter when MSG, else write edge_delta)
template <bool MSG>
__global__ void k_edge(const float* __restrict__ E, const int* __restrict__ edges,
                       const float* __restrict__ W1, const float* __restrict__ b1,
                       const float* __restrict__ W2, const float* __restrict__ b2,
                       const float* __restrict__ Wa1, const float* __restrict__ ba1,
                       const float* __restrict__ Wa2, const float* __restrict__ ba2,
                       const float* __restrict__ P, float* __restrict__ outE) {
    extern __shared__ float sm[];
    float2* sW1 = (float2*)sm;              // 8192 floats
    float4* sW2 = (float4*)(sm + 8192);     // 8192 floats
    float2* sB1 = (float2*)(sm + 16384);    // 64
    float4* sB2 = (float4*)(sm + 16448);    // 128
    float4* sWa1 = (float4*)(sm + 16576);   // 2048
    float* sBa1 = sm + 18624;               // 16
    float* sWa2 = sm + 18640;               // 16
    float* sE = sm + 18656;                 // 2048 -> total 20704 floats
    for (int i = threadIdx.x; i < 128 * 32; i += TPB) {
        int k = i >> 5, l = i & 31;
        sW1[i] = make_float2(W1[(256 + k) * 64 + l], W1[(256 + k) * 64 + l + 32]);
    }
    for (int i = threadIdx.x; i < 64 * 32; i += TPB) {
        int j = i >> 5, l = i & 31;
        sW2[i] = make_float4(W2[j * 128 + 4 * l], W2[j * 128 + 4 * l + 1],
                             W2[j * 128 + 4 * l + 2], W2[j * 128 + 4 * l + 3]);
    }
    if (MSG)
        for (int i = threadIdx.x; i < 16 * 32; i += TPB) {
            int j = i >> 5, l = i & 31;
            sWa1[i] = make_float4(Wa1[(4 * l) * 16 + j], Wa1[(4 * l + 1) * 16 + j],
                                  Wa1[(4 * l + 2) * 16 + j], Wa1[(4 * l + 3) * 16 + j]);
        }
    if (threadIdx.x < 32) {
        sB1[threadIdx.x] = make_float2(b1[threadIdx.x], b1[threadIdx.x + 32]);
        sB2[threadIdx.x] = make_float4(b2[4 * threadIdx.x], b2[4 * threadIdx.x + 1],
                                       b2[4 * threadIdx.x + 2], b2[4 * threadIdx.x + 3]);
    }
    if (MSG && threadIdx.x >= 32 && threadIdx.x < 48) {
        int j = threadIdx.x - 32; sBa1[j] = ba1[j]; sWa2[j] = Wa2[j];
    }
    const float ba2v = MSG ? ba2[0] : 0.f;
    __syncthreads();
    const ull* w1u = (const ull*)sW1;
    const ull* w2u = (const ull*)sW2;
    const ull* wau = (const ull*)sWa1;
    const int warp = threadIdx.x >> 5, l = threadIdx.x & 31;
    const int ntiles = (BSZ * NEg) / TILE;
    for (int t = blockIdx.x; t < ntiles; t += gridDim.x) {
        __syncthreads();
        const float4* Eg = (const float4*)E + (size_t)t * TILE * 32;
        for (int i = threadIdx.x; i < TILE * 32; i += TPB) ((float4*)sE)[i] = __ldcs(Eg + i);
        __syncthreads();
        const int ge0 = t * TILE + 2 * warp;
        const int b = ge0 / NEg;
        int2 ed0 = ((const int2*)edges)[ge0];
        int2 ed1 = ((const int2*)edges)[ge0 + 1];
        const float* Pb = P + (size_t)b * NN * 128;
        float2 bb = sB1[l];
        const float *s0 = Pb + (size_t)ed0.x * 128, *r0p = Pb + (size_t)ed0.y * 128;
        const float *s1 = Pb + (size_t)ed1.x * 128, *r1p = Pb + (size_t)ed1.y * 128;
        ull h0 = pk2(s0[l] + r0p[64 + l] + bb.x, s0[l + 32] + r0p[96 + l] + bb.y);
        ull h1 = pk2(s1[l] + r1p[64 + l] + bb.x, s1[l + 32] + r1p[96 + l] + bb.y);
        const float4* e0p = (const float4*)(sE + (2 * warp) * 128);
        const float4* e1p = e0p + 32;
#pragma unroll 4
        for (int k4 = 0; k4 < 32; k4++) {
            float ea[4], eb[4];
            *(float4*)ea = e0p[k4]; *(float4*)eb = e1p[k4];
#pragma unroll
            for (int i = 0; i < 4; i++) {
                ull w = w1u[(k4 * 4 + i) * 32 + l];
                h0 = fma2(dup2(ea[i]), w, h0);
                h1 = fma2(dup2(eb[i]), w, h1);
            }
        }
        float2 H0 = up2(h0), H1 = up2(h1);
        H0.x = silu_f(H0.x); H0.y = silu_f(H0.y);
        H1.x = silu_f(H1.x); H1.y = silu_f(H1.y);
        float4 b2v = sB2[l];
        ull m0a = pk2(b2v.x, b2v.y), m0b = pk2(b2v.z, b2v.w);
        ull m1a = m0a, m1b = m0b;
        gemm2(w2u, l, H0, H1, m0a, m0b, m1a, m1b);
        if (!MSG) {
            float2 A0 = up2(m0a), B0 = up2(m0b), A1 = up2(m1a), B1 = up2(m1b);
            float4* o = (float4*)outE + (size_t)ge0 * 32 + l;
            __stcs(o, make_float4(A0.x, A0.y, B0.x, B0.y));
            __stcs(o + 32, make_float4(A1.x, A1.y, B1.x, B1.y));
        } else {
#pragma unroll
            for (int eidx = 0; eidx < 2; eidx++) {
                ull ma = eidx ? m1a : m0a;
                ull mb = eidx ? m1b : m0b;
                int dst = eidx ? ed1.y : ed0.y;
                float logit = ba2v;
#pragma unroll
                for (int j = 0; j < 16; j++) {
                    ull acc = fma2(ma, wau[(j * 32 + l) * 2], 0ULL);
                    acc = fma2(mb, wau[(j * 32 + l) * 2 + 1], acc);
                    float2 a = up2(acc);
                    float p = a.x + a.y;
#pragma unroll
                    for (int off = 16; off; off >>= 1) p += __shfl_xor_sync(0xffffffffu, p, off);
                    logit += silu_f(p + sBa1[j]) * sWa2[j];
                }
                logit = fminf(30.f, fmaxf(-30.f, logit));
                float ex = __expf(logit);
                if (l == 0) atomicAdd(&g_den[b * NN + dst], ex);
                float2 MA = up2(ma), MB = up2(mb);
                float* ap = g_agg + (size_t)(b * NN + dst) * 128 + 4 * l;
                red4(ap, ex * MA.x, ex * MA.y, ex * MB.x, ex * MB.y);
            }
        }
    }
}

// node output MLP: concat(V, agg/den) -> 64 -> 128
__global__ void k_node_out(const float* __restrict__ V,
                           const float* __restrict__ Wn1, const float* __restrict__ bn1,
                           const float* __restrict__ Wn2, const float* __restrict__ bn2,
                           float* __restrict__ outN) {
    extern __shared__ float sm[];
    float2* sW1 = (float2*)sm;               // 16384 floats
    float4* sW2 = (float4*)(sm + 16384);     // 8192
    float2* sB1 = (float2*)(sm + 24576);     // 64
    float4* sB2 = (float4*)(sm + 24640);     // 128
    float* sInv = sm + 24768;                // 16
    float* sIn = sm + 24784;                 // 4096 -> 28880 floats
    for (int i = threadIdx.x; i < 256 * 32; i += TPB) {
        int k = i >> 5, l = i & 31;
        sW1[i] = make_float2(Wn1[k * 64 + l], Wn1[k * 64 + l + 32]);
    }
    for (int i = threadIdx.x; i < 64 * 32; i += TPB) {
        int j = i >> 5, l = i & 31;
        sW2[i] = make_float4(Wn2[j * 128 + 4 * l], Wn2[j * 128 + 4 * l + 1],
                             Wn2[j * 128 + 4 * l + 2], Wn2[j * 128 + 4 * l + 3]);
    }
    if (threadIdx.x < 32) {
        sB1[threadIdx.x] = make_float2(bn1[threadIdx.x], bn1[threadIdx.x + 32]);
        sB2[threadIdx.x] = make_float4(bn2[4 * threadIdx.x], bn2[4 * threadIdx.x + 1],
                                       bn2[4 * threadIdx.x + 2], bn2[4 * threadIdx.x + 3]);
    }
    __syncthreads();
    const ull* w1u = (const ull*)sW1;
    const ull* w2u = (const ull*)sW2;
    const int warp = threadIdx.x >> 5, l = threadIdx.x & 31;
    const int ntiles = (BSZ * NN) / TILE;
    for (int t = blockIdx.x; t < ntiles; t += gridDim.x) {
        __syncthreads();
        if (threadIdx.x < TILE) {
            float d = g_den[t * TILE + threadIdx.x];
            sInv[threadIdx.x] = d != 0.f ? 1.f / d : 0.f;
        }
        __syncthreads();
        for (int i = threadIdx.x; i < TILE * 64; i += TPB) {
            int r = i >> 6, c4 = i & 63;
            size_t row = (size_t)t * TILE + r;
            float4 v;
            if (c4 < 32) v = __ldcs((const float4*)V + row * 32 + c4);
            else {
                v = ((const float4*)g_agg)[row * 32 + (c4 - 32)];
                float inv = sInv[r];
                v.x *= inv; v.y *= inv; v.z *= inv; v.w *= inv;
            }
            ((float4*)sIn)[i] = v;
        }
        __syncthreads();
        const int r0 = 2 * warp;
        float2 bb = sB1[l];
        ull h0 = pk2(bb.x, bb.y), h1 = h0;
        const float4* i0 = (const float4*)(sIn + r0 * 256);
        const float4* i1 = i0 + 64;
#pragma unroll 4
        for (int k4 = 0; k4 < 64; k4++) {
            float ea[4], eb[4];
            *(float4*)ea = i0[k4]; *(float4*)eb = i1[k4];
#pragma unroll
            for (int i = 0; i < 4; i++) {
                ull w = w1u[(k4 * 4 + i) * 32 + l];
                h0 = fma2(dup2(ea[i]), w, h0);
                h1 = fma2(dup2(eb[i]), w, h1);
            }
        }
        float2 H0 = up2(h0), H1 = up2(h1);
        H0.x = silu_f(H0.x); H0.y = silu_f(H0.y);
        H1.x = silu_f(H1.x); H1.y = silu_f(H1.y);
        float4 b2v = sB2[l];
        ull m0a = pk2(b2v.x, b2v.y), m0b = pk2(b2v.z, b2v.w);
        ull m1a = m0a, m1b = m0b;
        gemm2(w2u, l, H0, H1, m0a, m0b, m1a, m1b);
        float2 A0 = up2(m0a), B0 = up2(m0b), A1 = up2(m1a), B1 = up2(m1b);
        float4* o = (float4*)outN + ((size_t)t * TILE + r0) * 32 + l;
        __stcs(o, make_float4(A0.x, A0.y, B0.x, B0.y));
        __stcs(o + 32, make_float4(A1.x, A1.y, B1.x, B1.y));
    }
}

extern "C" void kernel_launch(void* const* d_in, const int* in_sizes, int n_in,
                              void* d_out, int out_size) {
    const float* V = (const float*)d_in[0];
    const float* E = (const float*)d_in[1];
    const int* edges = (const int*)d_in[2];
    const float* Wm1 = (const float*)d_in[3];
    const float* bm1 = (const float*)d_in[4];
    const float* Wm2 = (const float*)d_in[5];
    const float* bm2 = (const float*)d_in[6];
    const float* Wa1 = (const float*)d_in[7];
    const float* ba1 = (const float*)d_in[8];
    const float* Wa2 = (const float*)d_in[9];
    const float* ba2 = (const float*)d_in[10];
    const float* Wu1 = (const float*)d_in[11];
    const float* bu1 = (const float*)d_in[12];
    const float* Wu2 = (const float*)d_in[13];
    const float* bu2 = (const float*)d_in[14];
    const float* Wn1 = (const float*)d_in[15];
    const float* bn1 = (const float*)d_in[16];
    const float* Wn2 = (const float*)d_in[17];
    const float* bn2 = (const float*)d_in[18];
    float* outN = (float*)d_out;
    float* outE = outN + (size_t)BSZ * NN * 128;

    float* Pmsg; cudaGetSymbolAddress((void**)&Pmsg, g_Pmsg);
    float* Pupd; cudaGetSymbolAddress((void**)&Pupd, g_Pupd);

    static int configured = 0;
    if (!configured) {
        cudaFuncSetAttribute(k_node_pre, cudaFuncAttributeMaxDynamicSharedMemorySize, 73728);
        cudaFuncSetAttribute(k_edge<true>, cudaFuncAttributeMaxDynamicSharedMemorySize, 82816);
        cudaFuncSetAttribute(k_edge<false>, cudaFuncAttributeMaxDynamicSharedMemorySize, 82816);
        cudaFuncSetAttribute(k_node_out, cudaFuncAttributeMaxDynamicSharedMemorySize, 115520);
        configured = 1;
    }

    k_init<<<296, TPB>>>();
    k_node_pre<<<592, TPB, 73728>>>(V, Wm1, Pmsg);
    k_node_pre<<<592, TPB, 73728>>>(V, Wu1, Pupd);
    k_edge<true><<<592, TPB, 82816>>>(E, edges, Wm1, bm1, Wm2, bm2, Wa1, ba1, Wa2, ba2, Pmsg, nullptr);
    k_edge<false><<<592, TPB, 82816>>>(E, edges, Wu1, bu1, Wu2, bu2, nullptr, nullptr, nullptr, nullptr, Pupd, outE);
    k_node_out<<<592, TPB, 115520>>>(V, Wn1, bn1, Wn2, bn2, outN);
}

// round 3
// speedup vs baseline: 1.7281x; 1.7281x over previous
#include <cuda_runtime.h>

typedef unsigned long long ull;
#define BSZ 2
#define NN 50000
#define NEg 400000
#define TPB 256
#define TILE 32   // edges per CTA iteration (8 warps * 4 edges)

__device__ float g_Pmsg[BSZ * NN * 128];
__device__ float g_Pupd[BSZ * NN * 128];
__device__ float g_agg[BSZ * NN * 128];
__device__ float g_den[BSZ * NN];
__device__ ull   g_Wf[16 * 32];   // fused W2@Wa1, packed per (j, lane): (Wf[l][j], Wf[l+32][j])
__device__ float g_bf[16];        // b2@Wa1 + ba1

__device__ __forceinline__ ull fma2(ull a, ull b, ull c) {
    ull d; asm("fma.rn.f32x2 %0, %1, %2, %3;" : "=l"(d) : "l"(a), "l"(b), "l"(c)); return d;
}
__device__ __forceinline__ ull add2(ull a, ull b) {
    ull d; asm("add.rn.f32x2 %0, %1, %2;" : "=l"(d) : "l"(a), "l"(b)); return d;
}
__device__ __forceinline__ ull mul2(ull a, ull b) {
    ull d; asm("mul.rn.f32x2 %0, %1, %2;" : "=l"(d) : "l"(a), "l"(b)); return d;
}
__device__ __forceinline__ ull pk2(float x, float y) {
    ull r; asm("mov.b64 %0, {%1, %2};" : "=l"(r) : "f"(x), "f"(y)); return r;
}
__device__ __forceinline__ ull dup2(float x) {
    ull r; asm("mov.b64 %0, {%1, %1};" : "=l"(r) : "f"(x)); return r;
}
__device__ __forceinline__ float2 up2(ull v) {
    float2 r; asm("mov.b64 {%0, %1}, %2;" : "=f"(r.x), "=f"(r.y) : "l"(v)); return r;
}
__device__ __forceinline__ float silu_f(float x) { return x / (1.f + __expf(-x)); }
__device__ __forceinline__ void red4(float* p, float a, float b, float c, float d) {
    asm volatile("red.global.add.v4.f32 [%0], {%1,%2,%3,%4};"
                 :: "l"(p), "f"(a), "f"(b), "f"(c), "f"(d) : "memory");
}

// legacy 64->128 gemm via shfl (kept for node_out)
__device__ __forceinline__ void gemm2(const ull* w2u, int l, float2 H0, float2 H1,
                                      ull& m0a, ull& m0b, ull& m1a, ull& m1b) {
#pragma unroll 4
    for (int j = 0; j < 32; j++) {
        ull wlo = w2u[(j * 32 + l) * 2], whi = w2u[(j * 32 + l) * 2 + 1];
        ull d0 = dup2(__shfl_sync(0xffffffffu, H0.x, j));
        ull d1 = dup2(__shfl_sync(0xffffffffu, H1.x, j));
        m0a = fma2(d0, wlo, m0a); m0b = fma2(d0, whi, m0b);
        m1a = fma2(d1, wlo, m1a); m1b = fma2(d1, whi, m1b);
    }
#pragma unroll 4
    for (int j = 0; j < 32; j++) {
        ull wlo = w2u[((j + 32) * 32 + l) * 2], whi = w2u[((j + 32) * 32 + l) * 2 + 1];
        ull d0 = dup2(__shfl_sync(0xffffffffu, H0.y, j));
        ull d1 = dup2(__shfl_sync(0xffffffffu, H1.y, j));
        m0a = fma2(d0, wlo, m0a); m0b = fma2(d0, whi, m0b);
        m1a = fma2(d1, wlo, m1a); m1b = fma2(d1, whi, m1b);
    }
}

__global__ void k_init() {
    float4 z = make_float4(0.f, 0.f, 0.f, 0.f);
    for (int i = blockIdx.x * blockDim.x + threadIdx.x; i < BSZ * NN * 32; i += gridDim.x * blockDim.x)
        ((float4*)g_agg)[i] = z;
    for (int i = blockIdx.x * blockDim.x + threadIdx.x; i < BSZ * NN; i += gridDim.x * blockDim.x)
        g_den[i] = 0.f;
}

// Wfuse = W2 @ Wa1 (64x16), bfuse = b2 @ Wa1 + ba1
__global__ void k_fuse(const float* __restrict__ W2, const float* __restrict__ b2,
                       const float* __restrict__ Wa1, const float* __restrict__ ba1) {
    int idx = blockIdx.x * blockDim.x + threadIdx.x;
    if (idx < 512) {
        int j = idx >> 5, l = idx & 31;
        float s0 = 0.f, s1 = 0.f;
        for (int c = 0; c < 128; c++) {
            float wa = Wa1[c * 16 + j];
            s0 += W2[l * 128 + c] * wa;
            s1 += W2[(l + 32) * 128 + c] * wa;
        }
        g_Wf[j * 32 + l] = pk2(s0, s1);
    }
    if (idx < 16) {
        float s = ba1[idx];
        for (int c = 0; c < 128; c++) s += b2[c] * Wa1[c * 16 + idx];
        g_bf[idx] = s;
    }
}

// per-node precompute; P row layout (as ull): [0..31]=sender pairs (h_l,h_{l+32}), [32..63]=receiver pairs
__global__ void k_node_pre(const float* __restrict__ V, const float* __restrict__ Wg, float* __restrict__ P) {
    extern __shared__ float sm[];
    float4* sW = (float4*)sm;           // 128*32 float4 = 64KB
    float* sV = sm + 128 * 32 * 4;      // 16*128
    for (int i = threadIdx.x; i < 128 * 32; i += TPB) {
        int k = i >> 5, l = i & 31;
        sW[i] = make_float4(Wg[k * 64 + l], Wg[k * 64 + l + 32],
                            Wg[(128 + k) * 64 + l], Wg[(128 + k) * 64 + l + 32]);
    }
    __syncthreads();
    const ull* sWu = (const ull*)sW;
    const int warp = threadIdx.x >> 5, l = threadIdx.x & 31;
    const int ntiles = (BSZ * NN) / 16;
    for (int t = blockIdx.x; t < ntiles; t += gridDim.x) {
        __syncthreads();
        const float4* Vg = (const float4*)V + (size_t)t * 16 * 32;
        for (int i = threadIdx.x; i < 16 * 32; i += TPB) ((float4*)sV)[i] = __ldcs(Vg + i);
        __syncthreads();
        const int r0 = 2 * warp;
        ull a0 = 0ULL, b0 = 0ULL, a1 = 0ULL, b1 = 0ULL;
        const float4* v0p = (const float4*)(sV + r0 * 128);
        const float4* v1p = v0p + 32;
#pragma unroll 4
        for (int k4 = 0; k4 < 32; k4++) {
            float ea[4], eb[4];
            *(float4*)ea = v0p[k4]; *(float4*)eb = v1p[k4];
#pragma unroll
            for (int i = 0; i < 4; i++) {
                int k = k4 * 4 + i;
                ull wa = sWu[(k * 32 + l) * 2], wb = sWu[(k * 32 + l) * 2 + 1];
                a0 = fma2(dup2(ea[i]), wa, a0); b0 = fma2(dup2(ea[i]), wb, b0);
                a1 = fma2(dup2(eb[i]), wa, a1); b1 = fma2(dup2(eb[i]), wb, b1);
            }
        }
        ull* p0 = (ull*)(P + ((size_t)t * 16 + r0) * 128);
        p0[l] = a0; p0[32 + l] = b0;
        ull* p1 = p0 + 64;
        p1[l] = a1; p1[32 + l] = b1;
    }
}

// fused edge MLP, 4 edges/warp. MSG: attention + scatter; else write edge_delta.
template <bool MSG>
__global__ void __launch_bounds__(TPB, 2)
k_edge(const float* __restrict__ E, const int* __restrict__ edges,
       const float* __restrict__ W1, const float* __restrict__ b1,
       const float* __restrict__ W2, const float* __restrict__ b2,
       const float* __restrict__ Wa2, const float* __restrict__ ba2,
       const float* __restrict__ P, float* __restrict__ outE) {
    extern __shared__ float sm[];
    ull*    sW1u = (ull*)sm;                 // 4096 ull (8192 floats)
    float4* sW1f = (float4*)sm;
    float4* sW2f = (float4*)(sm + 8192);     // 2048 float4 (8192 floats)
    float*  sE   = sm + 16384;               // 32*128 = 4096 floats
    float*  sH   = sm + 20480;               // 8 warps * 256 floats
    // total 22528 floats = 90112 B

    for (int i = threadIdx.x; i < 128 * 32; i += TPB) {
        int k = i >> 5, l = i & 31;
        sW1u[(k >> 1) * 64 + l * 2 + (k & 1)] =
            pk2(W1[(256 + k) * 64 + l], W1[(256 + k) * 64 + l + 32]);
    }
    for (int i = threadIdx.x; i < 64 * 32; i += TPB) {
        int j = i >> 5, l = i & 31;
        sW2f[i] = make_float4(W2[j * 128 + 4 * l], W2[j * 128 + 4 * l + 1],
                              W2[j * 128 + 4 * l + 2], W2[j * 128 + 4 * l + 3]);
    }
    const int warp = threadIdx.x >> 5, l = threadIdx.x & 31;
    const ull bbu  = pk2(__ldg(b1 + l), __ldg(b1 + l + 32));
    const ull b2lo = pk2(__ldg(b2 + 4 * l), __ldg(b2 + 4 * l + 1));
    const ull b2hi = pk2(__ldg(b2 + 4 * l + 2), __ldg(b2 + 4 * l + 3));
    // attention per-lane constants + fused weights in registers
    ull wf[16];
    float cBa = 0.f, cWa = 0.f, ba2v = 0.f;
    if (MSG) {
        int jl = ((l >> 4) & 1) * 8 + ((l >> 3) & 1) * 4 + ((l >> 2) & 1) * 2 + ((l >> 1) & 1);
        cBa = g_bf[jl];
        cWa = __ldg(Wa2 + jl) * 0.5f;   // each j appears on 2 lanes
        ba2v = __ldg(ba2);
#pragma unroll
        for (int j = 0; j < 16; j++) wf[j] = g_Wf[j * 32 + l];
    }
    __syncthreads();

    float* sHw = sH + warp * 256;
    const int ntiles = (BSZ * NEg) / TILE;
    for (int t = blockIdx.x; t < ntiles; t += gridDim.x) {
        __syncthreads();
        const float4* Eg = (const float4*)E + (size_t)t * TILE * 32;
        for (int i = threadIdx.x; i < TILE * 32; i += TPB) ((float4*)sE)[i] = __ldcs(Eg + i);
        __syncthreads();
        const int ge0 = t * TILE + warp * 4;
        const int b = ge0 / NEg;
        int4 eA = __ldg((const int4*)edges + ge0 / 2);
        int4 eB = __ldg((const int4*)edges + ge0 / 2 + 1);
        int sx[4] = {eA.x, eA.z, eB.x, eB.z};
        int rx[4] = {eA.y, eA.w, eB.y, eB.w};
        const ull* Pu = (const ull*)(P + (size_t)b * NN * 128);
        ull h[4];
#pragma unroll
        for (int e = 0; e < 4; e++) {
            ull sp = __ldg(Pu + (size_t)sx[e] * 64 + l);
            ull rp = __ldg(Pu + (size_t)rx[e] * 64 + 32 + l);
            h[e] = add2(add2(sp, rp), bbu);
        }
        const float4* er0 = (const float4*)(sE + (warp * 4) * 128);
#pragma unroll 8
        for (int k4 = 0; k4 < 32; k4++) {
            float4 e0 = er0[k4], e1 = er0[32 + k4], e2 = er0[64 + k4], e3 = er0[96 + k4];
            float4 wa = sW1f[(2 * k4) * 32 + l];
            float4 wb = sW1f[(2 * k4 + 1) * 32 + l];
            ull w0 = pk2(wa.x, wa.y), w1 = pk2(wa.z, wa.w);
            ull w2_ = pk2(wb.x, wb.y), w3 = pk2(wb.z, wb.w);
            h[0] = fma2(dup2(e0.x), w0, h[0]); h[0] = fma2(dup2(e0.y), w1, h[0]);
            h[0] = fma2(dup2(e0.z), w2_, h[0]); h[0] = fma2(dup2(e0.w), w3, h[0]);
            h[1] = fma2(dup2(e1.x), w0, h[1]); h[1] = fma2(dup2(e1.y), w1, h[1]);
            h[1] = fma2(dup2(e1.z), w2_, h[1]); h[1] = fma2(dup2(e1.w), w3, h[1]);
            h[2] = fma2(dup2(e2.x), w0, h[2]); h[2] = fma2(dup2(e2.y), w1, h[2]);
            h[2] = fma2(dup2(e2.z), w2_, h[2]); h[2] = fma2(dup2(e2.w), w3, h[2]);
            h[3] = fma2(dup2(e3.x), w0, h[3]); h[3] = fma2(dup2(e3.y), w1, h[3]);
            h[3] = fma2(dup2(e3.z), w2_, h[3]); h[3] = fma2(dup2(e3.w), w3, h[3]);
        }
        float2 SH[4];
        float ex[4];
#pragma unroll
        for (int e = 0; e < 4; e++) {
            float2 hh = up2(h[e]);
            SH[e].x = silu_f(hh.x); SH[e].y = silu_f(hh.y);
        }
        if (MSG) {
#pragma unroll
            for (int e = 0; e < 4; e++) {
                ull shp = pk2(SH[e].x, SH[e].y);
                float p[16];
#pragma unroll
                for (int j = 0; j < 16; j++) {
                    float2 a = up2(mul2(shp, wf[j]));
                    p[j] = a.x + a.y;
                }
#pragma unroll
                for (int j = 0; j < 16; j++) p[j] += __shfl_xor_sync(0xffffffffu, p[j], 16);
                float q[8];
#pragma unroll
                for (int j = 0; j < 8; j++) q[j] = (l & 16) ? p[j + 8] : p[j];
#pragma unroll
                for (int j = 0; j < 8; j++) q[j] += __shfl_xor_sync(0xffffffffu, q[j], 8);
                float r[4];
#pragma unroll
                for (int j = 0; j < 4; j++) r[j] = (l & 8) ? q[j + 4] : q[j];
#pragma unroll
                for (int j = 0; j < 4; j++) r[j] += __shfl_xor_sync(0xffffffffu, r[j], 4);
                float s2[2];
#pragma unroll
                for (int j = 0; j < 2; j++) s2[j] = (l & 4) ? r[j + 2] : r[j];
#pragma unroll
                for (int j = 0; j < 2; j++) s2[j] += __shfl_xor_sync(0xffffffffu, s2[j], 2);
                float tt = (l & 2) ? s2[1] : s2[0];
                tt += __shfl_xor_sync(0xffffffffu, tt, 1);
                float contrib = silu_f(tt + cBa) * cWa;
#pragma unroll
                for (int off = 16; off; off >>= 1) contrib += __shfl_xor_sync(0xffffffffu, contrib, off);
                float logit = fminf(30.f, fmaxf(-30.f, ba2v + contrib));
                ex[e] = __expf(logit);
            }
        }
        // stage h for broadcast
        sHw[l * 4 + 0] = SH[0].x; sHw[l * 4 + 1] = SH[1].x;
        sHw[l * 4 + 2] = SH[2].x; sHw[l * 4 + 3] = SH[3].x;
        sHw[(l + 32) * 4 + 0] = SH[0].y; sHw[(l + 32) * 4 + 1] = SH[1].y;
        sHw[(l + 32) * 4 + 2] = SH[2].y; sHw[(l + 32) * 4 + 3] = SH[3].y;
        __syncwarp();
        ull ma[4], mb[4];
#pragma unroll
        for (int e = 0; e < 4; e++) { ma[e] = b2lo; mb[e] = b2hi; }
        const float4* sHf = (const float4*)sHw;
#pragma unroll 8
        for (int j = 0; j < 64; j++) {
            float4 hj = sHf[j];
            float4 wv = sW2f[j * 32 + l];
            ull wlo = pk2(wv.x, wv.y), whi = pk2(wv.z, wv.w);
            ma[0] = fma2(dup2(hj.x), wlo, ma[0]); mb[0] = fma2(dup2(hj.x), whi, mb[0]);
            ma[1] = fma2(dup2(hj.y), wlo, ma[1]); mb[1] = fma2(dup2(hj.y), whi, mb[1]);
            ma[2] = fma2(dup2(hj.z), wlo, ma[2]); mb[2] = fma2(dup2(hj.z), whi, mb[2]);
            ma[3] = fma2(dup2(hj.w), wlo, ma[3]); mb[3] = fma2(dup2(hj.w), whi, mb[3]);
        }
        if (MSG) {
#pragma unroll
            for (int e = 0; e < 4; e++) {
                ull exd = dup2(ex[e]);
                float2 MA = up2(mul2(ma[e], exd)), MB = up2(mul2(mb[e], exd));
                float* ap = g_agg + (size_t)(b * NN + rx[e]) * 128 + 4 * l;
                red4(ap, MA.x, MA.y, MB.x, MB.y);
            }
            if (l < 4) atomicAdd(&g_den[b * NN + rx[l]], ex[l]);
        } else {
#pragma unroll
            for (int e = 0; e < 4; e++) {
                float2 MA = up2(ma[e]), MB = up2(mb[e]);
                __stcs((float4*)outE + (size_t)(ge0 + e) * 32 + l,
                       make_float4(MA.x, MA.y, MB.x, MB.y));
            }
        }
    }
}

// node output MLP: concat(V, agg/den) -> 64 -> 128
__global__ void k_node_out(const float* __restrict__ V,
                           const float* __restrict__ Wn1, const float* __restrict__ bn1,
                           const float* __restrict__ Wn2, const float* __restrict__ bn2,
                           float* __restrict__ outN) {
    extern __shared__ float sm[];
    float2* sW1 = (float2*)sm;               // 16384 floats
    float4* sW2 = (float4*)(sm + 16384);     // 8192
    float2* sB1 = (float2*)(sm + 24576);     // 64
    float4* sB2 = (float4*)(sm + 24640);     // 128
    float* sInv = sm + 24768;                // 16
    float* sIn = sm + 24784;                 // 4096 -> 28880 floats
    for (int i = threadIdx.x; i < 256 * 32; i += TPB) {
        int k = i >> 5, l = i & 31;
        sW1[i] = make_float2(Wn1[k * 64 + l], Wn1[k * 64 + l + 32]);
    }
    for (int i = threadIdx.x; i < 64 * 32; i += TPB) {
        int j = i >> 5, l = i & 31;
        sW2[i] = make_float4(Wn2[j * 128 + 4 * l], Wn2[j * 128 + 4 * l + 1],
                             Wn2[j * 128 + 4 * l + 2], Wn2[j * 128 + 4 * l + 3]);
    }
    if (threadIdx.x < 32) {
        sB1[threadIdx.x] = make_float2(bn1[threadIdx.x], bn1[threadIdx.x + 32]);
        sB2[threadIdx.x] = make_float4(bn2[4 * threadIdx.x], bn2[4 * threadIdx.x + 1],
                                       bn2[4 * threadIdx.x + 2], bn2[4 * threadIdx.x + 3]);
    }
    __syncthreads();
    const ull* w1u = (const ull*)sW1;
    const ull* w2u = (const ull*)sW2;
    const int warp = threadIdx.x >> 5, l = threadIdx.x & 31;
    const int ntiles = (BSZ * NN) / 16;
    for (int t = blockIdx.x; t < ntiles; t += gridDim.x) {
        __syncthreads();
        if (threadIdx.x < 16) {
            float d = g_den[t * 16 + threadIdx.x];
            sInv[threadIdx.x] = d != 0.f ? 1.f / d : 0.f;
        }
        __syncthreads();
        for (int i = threadIdx.x; i < 16 * 64; i += TPB) {
            int r = i >> 6, c4 = i & 63;
            size_t row = (size_t)t * 16 + r;
            float4 v;
            if (c4 < 32) v = __ldcs((const float4*)V + row * 32 + c4);
            else {
                v = ((const float4*)g_agg)[row * 32 + (c4 - 32)];
                float inv = sInv[r];
                v.x *= inv; v.y *= inv; v.z *= inv; v.w *= inv;
            }
            ((float4*)sIn)[i] = v;
        }
        __syncthreads();
        const int r0 = 2 * warp;
        float2 bb = sB1[l];
        ull h0 = pk2(bb.x, bb.y), h1 = h0;
        const float4* i0 = (const float4*)(sIn + r0 * 256);
        const float4* i1 = i0 + 64;
#pragma unroll 4
        for (int k4 = 0; k4 < 64; k4++) {
            float ea[4], eb[4];
            *(float4*)ea = i0[k4]; *(float4*)eb = i1[k4];
#pragma unroll
            for (int i = 0; i < 4; i++) {
                ull w = w1u[(k4 * 4 + i) * 32 + l];
                h0 = fma2(dup2(ea[i]), w, h0);
                h1 = fma2(dup2(eb[i]), w, h1);
            }
        }
        float2 H0 = up2(h0), H1 = up2(h1);
        H0.x = silu_f(H0.x); H0.y = silu_f(H0.y);
        H1.x = silu_f(H1.x); H1.y = silu_f(H1.y);
        float4 b2v = sB2[l];
        ull m0a = pk2(b2v.x, b2v.y), m0b = pk2(b2v.z, b2v.w);
        ull m1a = m0a, m1b = m0b;
        gemm2(w2u, l, H0, H1, m0a, m0b, m1a, m1b);
        float2 A0 = up2(m0a), B0 = up2(m0b), A1 = up2(m1a), B1 = up2(m1b);
        float4* o = (float4*)outN + ((size_t)t * 16 + r0) * 32 + l;
        __stcs(o, make_float4(A0.x, A0.y, B0.x, B0.y));
        __stcs(o + 32, make_float4(A1.x, A1.y, B1.x, B1.y));
    }
}

extern "C" void kernel_launch(void* const* d_in, const int* in_sizes, int n_in,
                              void* d_out, int out_size) {
    const float* V = (const float*)d_in[0];
    const float* E = (const float*)d_in[1];
    const int* edges = (const int*)d_in[2];
    const float* Wm1 = (const float*)d_in[3];
    const float* bm1 = (const float*)d_in[4];
    const float* Wm2 = (const float*)d_in[5];
    const float* bm2 = (const float*)d_in[6];
    const float* Wa1 = (const float*)d_in[7];
    const float* ba1 = (const float*)d_in[8];
    const float* Wa2 = (const float*)d_in[9];
    const float* ba2 = (const float*)d_in[10];
    const float* Wu1 = (const float*)d_in[11];
    const float* bu1 = (const float*)d_in[12];
    const float* Wu2 = (const float*)d_in[13];
    const float* bu2 = (const float*)d_in[14];
    const float* Wn1 = (const float*)d_in[15];
    const float* bn1 = (const float*)d_in[16];
    const float* Wn2 = (const float*)d_in[17];
    const float* bn2 = (const float*)d_in[18];
    float* outN = (float*)d_out;
    float* outE = outN + (size_t)BSZ * NN * 128;

    float* Pmsg; cudaGetSymbolAddress((void**)&Pmsg, g_Pmsg);
    float* Pupd; cudaGetSymbolAddress((void**)&Pupd, g_Pupd);

    cudaFuncSetAttribute(k_node_pre, cudaFuncAttributeMaxDynamicSharedMemorySize, 73728);
    cudaFuncSetAttribute(k_edge<true>, cudaFuncAttributeMaxDynamicSharedMemorySize, 90112);
    cudaFuncSetAttribute(k_edge<false>, cudaFuncAttributeMaxDynamicSharedMemorySize, 90112);
    cudaFuncSetAttribute(k_node_out, cudaFuncAttributeMaxDynamicSharedMemorySize, 115520);

    k_init<<<296, TPB>>>();
    k_fuse<<<2, TPB>>>(Wm2, bm2, Wa1, ba1);
    k_node_pre<<<592, TPB, 73728>>>(V, Wm1, Pmsg);
    k_node_pre<<<592, TPB, 73728>>>(V, Wu1, Pupd);
    k_edge<true><<<592, TPB, 90112>>>(E, edges, Wm1, bm1, Wm2, bm2, Wa2, ba2, Pmsg, nullptr);
    k_edge<false><<<592, TPB, 90112>>>(E, edges, Wu1, bu1, Wu2, bu2, nullptr, nullptr, Pupd, outE);
    k_node_out<<<592, TPB, 115520>>>(V, Wn1, bn1, Wn2, bn2, outN);
}

// round 4
// speedup vs baseline: 1.9397x; 1.1224x over previous
#include <cuda_runtime.h>

typedef unsigned long long ull;
#define BSZ 2
#define NN 50000
#define NEg 400000
#define TPB 256

__device__ float g_Pmsg[BSZ * NN * 128];
__device__ float g_Pupd[BSZ * NN * 128];
__device__ float g_agg[BSZ * NN * 128];
__device__ float g_den[BSZ * NN];
__device__ float4 g_Wf4[256];   // fused W2@Wa1 as [c][j] floats, float4 over j
__device__ float g_bf[16];      // b2@Wa1 + ba1

__device__ __forceinline__ ull fma2(ull a, ull b, ull c) {
    ull d; asm("fma.rn.f32x2 %0, %1, %2, %3;" : "=l"(d) : "l"(a), "l"(b), "l"(c)); return d;
}
__device__ __forceinline__ ull add2(ull a, ull b) {
    ull d; asm("add.rn.f32x2 %0, %1, %2;" : "=l"(d) : "l"(a), "l"(b)); return d;
}
__device__ __forceinline__ ull mul2(ull a, ull b) {
    ull d; asm("mul.rn.f32x2 %0, %1, %2;" : "=l"(d) : "l"(a), "l"(b)); return d;
}
__device__ __forceinline__ ull pk2(float x, float y) {
    ull r; asm("mov.b64 %0, {%1, %2};" : "=l"(r) : "f"(x), "f"(y)); return r;
}
__device__ __forceinline__ ull dup2(float x) {
    ull r; asm("mov.b64 %0, {%1, %1};" : "=l"(r) : "f"(x)); return r;
}
__device__ __forceinline__ float2 up2(ull v) {
    float2 r; asm("mov.b64 {%0, %1}, %2;" : "=f"(r.x), "=f"(r.y) : "l"(v)); return r;
}
__device__ __forceinline__ float silu_f(float x) { return x / (1.f + __expf(-x)); }
__device__ __forceinline__ void red4(float* p, float a, float b, float c, float d) {
    asm volatile("red.global.add.v4.f32 [%0], {%1,%2,%3,%4};"
                 :: "l"(p), "f"(a), "f"(b), "f"(c), "f"(d) : "memory");
}

// 64->128 gemm via shfl (node_out only)
__device__ __forceinline__ void gemm2(const ull* w2u, int l, float2 H0, float2 H1,
                                      ull& m0a, ull& m0b, ull& m1a, ull& m1b) {
#pragma unroll 4
    for (int j = 0; j < 32; j++) {
        ull wlo = w2u[(j * 32 + l) * 2], whi = w2u[(j * 32 + l) * 2 + 1];
        ull d0 = dup2(__shfl_sync(0xffffffffu, H0.x, j));
        ull d1 = dup2(__shfl_sync(0xffffffffu, H1.x, j));
        m0a = fma2(d0, wlo, m0a); m0b = fma2(d0, whi, m0b);
        m1a = fma2(d1, wlo, m1a); m1b = fma2(d1, whi, m1b);
    }
#pragma unroll 4
    for (int j = 0; j < 32; j++) {
        ull wlo = w2u[((j + 32) * 32 + l) * 2], whi = w2u[((j + 32) * 32 + l) * 2 + 1];
        ull d0 = dup2(__shfl_sync(0xffffffffu, H0.y, j));
        ull d1 = dup2(__shfl_sync(0xffffffffu, H1.y, j));
        m0a = fma2(d0, wlo, m0a); m0b = fma2(d0, whi, m0b);
        m1a = fma2(d1, wlo, m1a); m1b = fma2(d1, whi, m1b);
    }
}

__global__ void k_init() {
    float4 z = make_float4(0.f, 0.f, 0.f, 0.f);
    for (int i = blockIdx.x * blockDim.x + threadIdx.x; i < BSZ * NN * 32; i += gridDim.x * blockDim.x)
        ((float4*)g_agg)[i] = z;
    for (int i = blockIdx.x * blockDim.x + threadIdx.x; i < BSZ * NN; i += gridDim.x * blockDim.x)
        g_den[i] = 0.f;
}

// Wf[c][j] = sum_d W2[c][d]*Wa1[d][j];  bf[j] = b2@Wa1 + ba1
__global__ void k_fuse(const float* __restrict__ W2, const float* __restrict__ b2,
                       const float* __restrict__ Wa1, const float* __restrict__ ba1) {
    int idx = blockIdx.x * blockDim.x + threadIdx.x;
    if (idx < 1024) {
        int c = idx >> 4, j = idx & 15;
        float s = 0.f;
        for (int d = 0; d < 128; d++) s += W2[c * 128 + d] * Wa1[d * 16 + j];
        ((float*)g_Wf4)[c * 16 + j] = s;
    }
    if (idx < 16) {
        float s = ba1[idx];
        for (int d = 0; d < 128; d++) s += b2[d] * Wa1[d * 16 + idx];
        g_bf[idx] = s;
    }
}

// per-node precompute, 4 rows/warp; P row (ull): [0..31]=sender pairs, [32..63]=receiver pairs
__global__ void k_node_pre(const float* __restrict__ V, const float* __restrict__ Wg, float* __restrict__ P) {
    extern __shared__ float sm[];
    float4* sW = (float4*)sm;           // 4096 float4 (64KB)
    float* sV = sm + 16384;             // 32*128 = 4096 floats (16KB)
    for (int i = threadIdx.x; i < 128 * 32; i += TPB) {
        int k = i >> 5, l = i & 31;
        sW[i] = make_float4(Wg[k * 64 + l], Wg[k * 64 + l + 32],
                            Wg[(128 + k) * 64 + l], Wg[(128 + k) * 64 + l + 32]);
    }
    __syncthreads();
    const ull* sWu = (const ull*)sW;
    const int warp = threadIdx.x >> 5, l = threadIdx.x & 31;
    const int ntiles = (BSZ * NN) / 32;   // 3125
    for (int t = blockIdx.x; t < ntiles; t += gridDim.x) {
        __syncthreads();
        const float4* Vg = (const float4*)V + (size_t)t * 32 * 32;
        for (int i = threadIdx.x; i < 32 * 32; i += TPB) ((float4*)sV)[i] = __ldcs(Vg + i);
        __syncthreads();
        const int r0 = 4 * warp;
        ull a[4] = {0ULL, 0ULL, 0ULL, 0ULL}, bq[4] = {0ULL, 0ULL, 0ULL, 0ULL};
        const float4* sV4 = (const float4*)sV;
#pragma unroll 4
        for (int k4 = 0; k4 < 32; k4++) {
            ull wa[4], wb[4];
#pragma unroll
            for (int ki = 0; ki < 4; ki++) {
                int k = k4 * 4 + ki;
                wa[ki] = sWu[(k * 32 + l) * 2];
                wb[ki] = sWu[(k * 32 + l) * 2 + 1];
            }
#pragma unroll
            for (int r = 0; r < 4; r++) {
                float4 v = sV4[(r0 + r) * 32 + k4];
                a[r] = fma2(dup2(v.x), wa[0], a[r]); bq[r] = fma2(dup2(v.x), wb[0], bq[r]);
                a[r] = fma2(dup2(v.y), wa[1], a[r]); bq[r] = fma2(dup2(v.y), wb[1], bq[r]);
                a[r] = fma2(dup2(v.z), wa[2], a[r]); bq[r] = fma2(dup2(v.z), wb[2], bq[r]);
                a[r] = fma2(dup2(v.w), wa[3], a[r]); bq[r] = fma2(dup2(v.w), wb[3], bq[r]);
            }
        }
#pragma unroll
        for (int r = 0; r < 4; r++) {
            ull* p = (ull*)(P + ((size_t)t * 32 + r0 + r) * 128);
            p[l] = a[r]; p[32 + l] = bq[r];
        }
    }
}

// fused edge MLP, 8 edges/warp. MSG: attention + scatter; else write edge_delta.
template <bool MSG>
__global__ void __launch_bounds__(TPB, 2)
k_edge(const float* __restrict__ E, const int* __restrict__ edges,
       const float* __restrict__ W1, const float* __restrict__ b1,
       const float* __restrict__ W2, const float* __restrict__ b2,
       const float* __restrict__ Wa2, const float* __restrict__ ba2,
       const float* __restrict__ P, float* __restrict__ outE) {
    extern __shared__ float sm[];
    ull*    sW1u = (ull*)sm;                 // 4096 ull (floats 0..8192)
    float4* sW1f = (float4*)sm;
    float4* sW2f = (float4*)(sm + 8192);     // floats 8192..16384
    float4* sWfF = (float4*)(sm + 16384);    // 256 float4 (floats 16384..17408)
    float*  sBf  = sm + 17408;               // 16
    float*  sWa2s= sm + 17424;               // 16
    float*  sH   = sm + 17440;               // 8 warps * 8 edges * 72 = 4608
    // total 22048 floats = 88192 B

    for (int i = threadIdx.x; i < 128 * 32; i += TPB) {
        int k = i >> 5, l = i & 31;
        sW1u[(k >> 1) * 64 + l * 2 + (k & 1)] =
            pk2(W1[(256 + k) * 64 + l], W1[(256 + k) * 64 + l + 32]);
    }
    for (int i = threadIdx.x; i < 64 * 32; i += TPB) {
        int j = i >> 5, l = i & 31;
        sW2f[i] = make_float4(W2[j * 128 + 4 * l], W2[j * 128 + 4 * l + 1],
                              W2[j * 128 + 4 * l + 2], W2[j * 128 + 4 * l + 3]);
    }
    if (MSG) {
        for (int i = threadIdx.x; i < 256; i += TPB) sWfF[i] = g_Wf4[i];
        if (threadIdx.x < 16) { sBf[threadIdx.x] = g_bf[threadIdx.x]; sWa2s[threadIdx.x] = __ldg(Wa2 + threadIdx.x); }
    }
    const int warp = threadIdx.x >> 5, l = threadIdx.x & 31;
    const ull bbu  = pk2(__ldg(b1 + l), __ldg(b1 + l + 32));
    const ull b2lo = pk2(__ldg(b2 + 4 * l), __ldg(b2 + 4 * l + 1));
    const ull b2hi = pk2(__ldg(b2 + 4 * l + 2), __ldg(b2 + 4 * l + 3));
    const float ba2v = MSG ? __ldg(ba2) : 0.f;
    __syncthreads();

    float* sHw = sH + warp * 576;   // 8 rows * 72
    const int nchunks = (BSZ * NEg) / 8;       // 100000 chunks of 8 edges
    const int gw0 = blockIdx.x * 8 + warp;
    const int gstride = gridDim.x * 8;
    for (int w = gw0; w < nchunks; w += gstride) {
        const int ge0 = w * 8;
        const int b = ge0 / NEg;
        int sx[8], rx[8];
        const int2* edp = (const int2*)edges + ge0;
#pragma unroll
        for (int e = 0; e < 8; e++) { int2 t2 = __ldg(edp + e); sx[e] = t2.x; rx[e] = t2.y; }
        const ull* Pu = (const ull*)P + (size_t)b * NN * 64;
        ull h[8];
#pragma unroll
        for (int e = 0; e < 8; e++) {
            ull sp = __ldg(Pu + (size_t)sx[e] * 64 + l);
            ull rp = __ldg(Pu + (size_t)rx[e] * 64 + 32 + l);
            h[e] = add2(add2(sp, rp), bbu);
        }
        const float4* Ef = (const float4*)E + (size_t)ge0 * 32;
#pragma unroll 4
        for (int k4 = 0; k4 < 32; k4++) {
            float4 wa = sW1f[(2 * k4) * 32 + l];
            float4 wb = sW1f[(2 * k4 + 1) * 32 + l];
            ull w0 = pk2(wa.x, wa.y), w1 = pk2(wa.z, wa.w);
            ull w2_ = pk2(wb.x, wb.y), w3 = pk2(wb.z, wb.w);
#pragma unroll
            for (int e = 0; e < 8; e++) {
                float4 ev = __ldg(Ef + e * 32 + k4);
                h[e] = fma2(dup2(ev.x), w0, h[e]);
                h[e] = fma2(dup2(ev.y), w1, h[e]);
                h[e] = fma2(dup2(ev.z), w2_, h[e]);
                h[e] = fma2(dup2(ev.w), w3, h[e]);
            }
        }
        __syncwarp();
#pragma unroll
        for (int e = 0; e < 8; e++) {
            float2 hh = up2(h[e]);
            sHw[e * 72 + l] = silu_f(hh.x);
            sHw[e * 72 + l + 32] = silu_f(hh.y);
        }
        __syncwarp();
        // attention: lanes = (jg = l>>3) x (e = l&7); p = sh @ Wf
        float ex[8]; float exf = 0.f;
        if (MSG) {
            const int e_att = l & 7, jg = l >> 3;
            const float* shrow = sHw + e_att * 72;
            float p0 = 0.f, p1 = 0.f, p2 = 0.f, p3 = 0.f;
#pragma unroll 8
            for (int c = 0; c < 64; c++) {
                float shc = shrow[c];
                float4 wfv = sWfF[c * 4 + jg];
                p0 += shc * wfv.x; p1 += shc * wfv.y;
                p2 += shc * wfv.z; p3 += shc * wfv.w;
            }
            float s = silu_f(p0 + sBf[jg * 4 + 0]) * sWa2s[jg * 4 + 0]
                    + silu_f(p1 + sBf[jg * 4 + 1]) * sWa2s[jg * 4 + 1]
                    + silu_f(p2 + sBf[jg * 4 + 2]) * sWa2s[jg * 4 + 2]
                    + silu_f(p3 + sBf[jg * 4 + 3]) * sWa2s[jg * 4 + 3];
            s += __shfl_xor_sync(0xffffffffu, s, 8);
            s += __shfl_xor_sync(0xffffffffu, s, 16);
            float logit = fminf(30.f, fmaxf(-30.f, ba2v + s));
            exf = __expf(logit);
#pragma unroll
            for (int e = 0; e < 8; e++) ex[e] = __shfl_sync(0xffffffffu, exf, e);
        }
        // stage 2: m = silu_h @ W2 + b2
        ull ma[8], mb[8];
#pragma unroll
        for (int e = 0; e < 8; e++) { ma[e] = b2lo; mb[e] = b2hi; }
#pragma unroll 2
        for (int c4 = 0; c4 < 16; c4++) {
            float4 hh[8];
#pragma unroll
            for (int e = 0; e < 8; e++) hh[e] = *(const float4*)(sHw + e * 72 + 4 * c4);
#pragma unroll
            for (int ci = 0; ci < 4; ci++) {
                int c = 4 * c4 + ci;
                float4 wv = sW2f[c * 32 + l];
                ull wlo = pk2(wv.x, wv.y), whi = pk2(wv.z, wv.w);
#pragma unroll
                for (int e = 0; e < 8; e++) {
                    float hv = (ci == 0) ? hh[e].x : (ci == 1) ? hh[e].y : (ci == 2) ? hh[e].z : hh[e].w;
                    ull d = dup2(hv);
                    ma[e] = fma2(d, wlo, ma[e]);
                    mb[e] = fma2(d, whi, mb[e]);
                }
            }
        }
        if (MSG) {
#pragma unroll
            for (int e = 0; e < 8; e++) {
                ull exd = dup2(ex[e]);
                float2 MA = up2(mul2(ma[e], exd)), MB = up2(mul2(mb[e], exd));
                float* ap = g_agg + (size_t)(b * NN + rx[e]) * 128 + 4 * l;
                red4(ap, MA.x, MA.y, MB.x, MB.y);
            }
            if (l < 8) {
                int2 t2 = __ldg(edp + l);
                atomicAdd(&g_den[b * NN + t2.y], exf);
            }
        } else {
#pragma unroll
            for (int e = 0; e < 8; e++) {
                float2 MA = up2(ma[e]), MB = up2(mb[e]);
                __stcs((float4*)outE + (size_t)(ge0 + e) * 32 + l,
                       make_float4(MA.x, MA.y, MB.x, MB.y));
            }
        }
        __syncwarp();
    }
}

// node output MLP: concat(V, agg/den) -> 64 -> 128
__global__ void k_node_out(const float* __restrict__ V,
                           const float* __restrict__ Wn1, const float* __restrict__ bn1,
                           const float* __restrict__ Wn2, const float* __restrict__ bn2,
                           float* __restrict__ outN) {
    extern __shared__ float sm[];
    float2* sW1 = (float2*)sm;               // 16384 floats
    float4* sW2 = (float4*)(sm + 16384);     // 8192
    float2* sB1 = (float2*)(sm + 24576);     // 64
    float4* sB2 = (float4*)(sm + 24640);     // 128
    float* sInv = sm + 24768;                // 16
    float* sIn = sm + 24784;                 // 4096 -> 28880 floats
    for (int i = threadIdx.x; i < 256 * 32; i += TPB) {
        int k = i >> 5, l = i & 31;
        sW1[i] = make_float2(Wn1[k * 64 + l], Wn1[k * 64 + l + 32]);
    }
    for (int i = threadIdx.x; i < 64 * 32; i += TPB) {
        int j = i >> 5, l = i & 31;
        sW2[i] = make_float4(Wn2[j * 128 + 4 * l], Wn2[j * 128 + 4 * l + 1],
                             Wn2[j * 128 + 4 * l + 2], Wn2[j * 128 + 4 * l + 3]);
    }
    if (threadIdx.x < 32) {
        sB1[threadIdx.x] = make_float2(bn1[threadIdx.x], bn1[threadIdx.x + 32]);
        sB2[threadIdx.x] = make_float4(bn2[4 * threadIdx.x], bn2[4 * threadIdx.x + 1],
                                       bn2[4 * threadIdx.x + 2], bn2[4 * threadIdx.x + 3]);
    }
    __syncthreads();
    const ull* w1u = (const ull*)sW1;
    const ull* w2u = (const ull*)sW2;
    const int warp = threadIdx.x >> 5, l = threadIdx.x & 31;
    const int ntiles = (BSZ * NN) / 16;
    for (int t = blockIdx.x; t < ntiles; t += gridDim.x) {
        __syncthreads();
        if (threadIdx.x < 16) {
            float d = g_den[t * 16 + threadIdx.x];
            sInv[threadIdx.x] = d != 0.f ? 1.f / d : 0.f;
        }
        __syncthreads();
        for (int i = threadIdx.x; i < 16 * 64; i += TPB) {
            int r = i >> 6, c4 = i & 63;
            size_t row = (size_t)t * 16 + r;
            float4 v;
            if (c4 < 32) v = __ldcs((const float4*)V + row * 32 + c4);
            else {
                v = ((const float4*)g_agg)[row * 32 + (c4 - 32)];
                float inv = sInv[r];
                v.x *= inv; v.y *= inv; v.z *= inv; v.w *= inv;
            }
            ((float4*)sIn)[i] = v;
        }
        __syncthreads();
        const int r0 = 2 * warp;
        float2 bb = sB1[l];
        ull h0 = pk2(bb.x, bb.y), h1 = h0;
        const float4* i0 = (const float4*)(sIn + r0 * 256);
        const float4* i1 = i0 + 64;
#pragma unroll 4
        for (int k4 = 0; k4 < 64; k4++) {
            float ea[4], eb[4];
            *(float4*)ea = i0[k4]; *(float4*)eb = i1[k4];
#pragma unroll
            for (int i = 0; i < 4; i++) {
                ull w = w1u[(k4 * 4 + i) * 32 + l];
                h0 = fma2(dup2(ea[i]), w, h0);
                h1 = fma2(dup2(eb[i]), w, h1);
            }
        }
        float2 H0 = up2(h0), H1 = up2(h1);
        H0.x = silu_f(H0.x); H0.y = silu_f(H0.y);
        H1.x = silu_f(H1.x); H1.y = silu_f(H1.y);
        float4 b2v = sB2[l];
        ull m0a = pk2(b2v.x, b2v.y), m0b = pk2(b2v.z, b2v.w);
        ull m1a = m0a, m1b = m0b;
        gemm2(w2u, l, H0, H1, m0a, m0b, m1a, m1b);
        float2 A0 = up2(m0a), B0 = up2(m0b), A1 = up2(m1a), B1 = up2(m1b);
        float4* o = (float4*)outN + ((size_t)t * 16 + r0) * 32 + l;
        __stcs(o, make_float4(A0.x, A0.y, B0.x, B0.y));
        __stcs(o + 32, make_float4(A1.x, A1.y, B1.x, B1.y));
    }
}

extern "C" void kernel_launch(void* const* d_in, const int* in_sizes, int n_in,
                              void* d_out, int out_size) {
    const float* V = (const float*)d_in[0];
    const float* E = (const float*)d_in[1];
    const int* edges = (const int*)d_in[2];
    const float* Wm1 = (const float*)d_in[3];
    const float* bm1 = (const float*)d_in[4];
    const float* Wm2 = (const float*)d_in[5];
    const float* bm2 = (const float*)d_in[6];
    const float* Wa1 = (const float*)d_in[7];
    const float* ba1 = (const float*)d_in[8];
    const float* Wa2 = (const float*)d_in[9];
    const float* ba2 = (const float*)d_in[10];
    const float* Wu1 = (const float*)d_in[11];
    const float* bu1 = (const float*)d_in[12];
    const float* Wu2 = (const float*)d_in[13];
    const float* bu2 = (const float*)d_in[14];
    const float* Wn1 = (const float*)d_in[15];
    const float* bn1 = (const float*)d_in[16];
    const float* Wn2 = (const float*)d_in[17];
    const float* bn2 = (const float*)d_in[18];
    float* outN = (float*)d_out;
    float* outE = outN + (size_t)BSZ * NN * 128;

    float* Pmsg; cudaGetSymbolAddress((void**)&Pmsg, g_Pmsg);
    float* Pupd; cudaGetSymbolAddress((void**)&Pupd, g_Pupd);

    cudaFuncSetAttribute(k_node_pre, cudaFuncAttributeMaxDynamicSharedMemorySize, 81920);
    cudaFuncSetAttribute(k_edge<true>, cudaFuncAttributeMaxDynamicSharedMemorySize, 88192);
    cudaFuncSetAttribute(k_edge<false>, cudaFuncAttributeMaxDynamicSharedMemorySize, 88192);
    cudaFuncSetAttribute(k_node_out, cudaFuncAttributeMaxDynamicSharedMemorySize, 115520);

    k_init<<<296, TPB>>>();
    k_fuse<<<8, TPB>>>(Wm2, bm2, Wa1, ba1);
    k_node_pre<<<592, TPB, 81920>>>(V, Wm1, Pmsg);
    k_node_pre<<<592, TPB, 81920>>>(V, Wu1, Pupd);
    k_edge<true><<<592, TPB, 88192>>>(E, edges, Wm1, bm1, Wm2, bm2, Wa2, ba2, Pmsg, nullptr);
    k_edge<false><<<592, TPB, 88192>>>(E, edges, Wu1, bu1, Wu2, bu2, nullptr, nullptr, Pupd, outE);
    k_node_out<<<592, TPB, 115520>>>(V, Wn1, bn1, Wn2, bn2, outN);
}